// round 13
// baseline (speedup 1.0000x reference)
#include <cuda_runtime.h>

#define NB 16          // batches per block
#define THREADS 384    // = NB * 12 * 2 (thread-pair per (batch,r))
#define RKSTRIDE 516   // 16*32 + 4 pad floats
#define TSTRIDE 36     // bucket-table row stride (bank spread)

__device__ float g_C[33 * TSTRIDE];   // C_k[c]: constant part of Ghat per bucket
__device__ float g_D[33 * TSTRIDE];   // D_k[c]: slope part of Ghat per bucket
__device__ float g_ts[32];            // sorted thresholds

__global__ __launch_bounds__(256, 1) void precompute_kernel(
        const float* __restrict__ qw1,
        const float* __restrict__ qb1,
        const float* __restrict__ qw2,
        const float* __restrict__ qb2,
        const float* __restrict__ kw2) {
    __shared__ float sW[32 * 32];
    __shared__ float su[32];
    __shared__ float th_raw[32];
    __shared__ float s_sgn[32];
    __shared__ int   sidx[32];

    int t = threadIdx.x;              // 256 threads
    for (int e = t; e < 1024; e += 256) {
        int j = e >> 5, jp = e & 31;
        float s = 0.f;
        #pragma unroll
        for (int h = 0; h < 64; ++h)
            s = fmaf(qw2[j * 64 + h], kw2[jp * 64 + h], s);
        sW[e] = s;
    }
    if (t < 32) {
        int jp = t;
        float su_ = 0.f;
        #pragma unroll
        for (int h = 0; h < 64; ++h)
            su_ = fmaf(qb2[h], kw2[jp * 64 + h], su_);
        su[jp] = su_;
        float w = qw1[jp], b = qb1[jp];
        float th, sg;
        if (w > 0.f)      { th = -b / w; sg = 1.f; }
        else if (w < 0.f) { th = -b / w; sg = -1.f; }
        else              { th = (b > 0.f) ? -1e30f : 1e30f; sg = 1.f; }
        th_raw[jp] = th;
        s_sgn[jp] = sg;
    }
    __syncthreads();
    if (t < 32) {
        float mt = th_raw[t];
        int r = 0;
        #pragma unroll
        for (int i = 0; i < 32; ++i) {
            float o = th_raw[i];
            if (o < mt || (o == mt && i < t)) ++r;
        }
        sidx[r] = t;
        g_ts[r] = mt;
    }
    __syncthreads();
    for (int task = t; task < 33 * 32; task += 256) {
        int k = task >> 5, c = task & 31;
        float C = su[c], D = 0.f;
        for (int i = 0; i < 32; ++i) {
            int o = sidx[i];
            bool pos = (s_sgn[o] > 0.f);
            bool active = pos ? (i < k) : (i >= k);
            if (active) {
                float wv = sW[o * 32 + c];
                C = fmaf(qb1[o], wv, C);
                D = fmaf(qw1[o], wv, D);
            }
        }
        g_C[k * TSTRIDE + c] = C;
        g_D[k * TSTRIDE + c] = D;
    }
}

__global__ __launch_bounds__(THREADS, 3) void nearfield_kernel(
    const float* __restrict__ rss_t,          // [B,12]
    const float* __restrict__ led_features,   // [B,16,8]
    const float* __restrict__ led_positions,  // [B,16,3]
    const float* __restrict__ prev_pos,       // [B,3]
    const int*   __restrict__ freq_mask,      // [12,16]
    const float* __restrict__ gw1, const float* __restrict__ gb1,
    const float* __restrict__ gw2, const float* __restrict__ gb2,
    const float* __restrict__ kw1, const float* __restrict__ kb1,
    const float* __restrict__ sigma,
    float* __restrict__ out_attn,             // [B,12,16]
    float* __restrict__ out_iw)               // [B,12]
{
    __shared__ __align__(16) float s_kw1[11 * 32];
    __shared__ __align__(16) float s_kb1[32];
    __shared__ __align__(16) float s_C[33 * TSTRIDE];
    __shared__ __align__(16) float s_D[33 * TSTRIDE];
    __shared__ __align__(16) float s_ts[32];
    __shared__ float s_gw1[16], s_gb1[16], s_gw2[16];
    __shared__ float s_gb2, s_scale;
    __shared__ unsigned s_mask[12];
    __shared__ __align__(16) float s_rk[NB * RKSTRIDE];
    __shared__ float s_dist[NB * 16];
    __shared__ float s_xv[NB * 12];           // x per (b,r)
    __shared__ int   s_krow[NB * 12];         // bucket row offset per (b,r)

    const int tid = threadIdx.x;

    // ---- cooperative staging ----
    for (int i = tid; i < 352; i += THREADS) s_kw1[i] = kw1[i];
    for (int i = tid; i < 33 * TSTRIDE; i += THREADS) {
        s_C[i] = g_C[i];
        s_D[i] = g_D[i];
    }
    if (tid < 32) {
        s_kb1[tid] = kb1[tid];
        s_ts[tid]  = g_ts[tid];
    }
    if (tid < 16) {
        s_gw1[tid] = gw1[tid];
        s_gb1[tid] = gb1[tid];
        s_gw2[tid] = gw2[tid];
    }
    if (tid == 0) {
        float sg = sigma[0];
        s_gb2 = gb2[0];
        s_scale = 0.5f / (sg * sg);
    }
    if (tid < 12) {
        unsigned m = 0;
        #pragma unroll
        for (int l = 0; l < 16; ++l)
            if (freq_mask[tid * 16 + l] != 0) m |= (1u << l);
        s_mask[tid] = m;
    }
    __syncthreads();

    const int block0 = blockIdx.x * NB;
    const float scale = s_scale;

    // ---- Phase K: subtask (b, l, half): 16 cols of rk = relu(led_in@kw1+kb1) ----
    for (int st = tid; st < NB * 16 * 2; st += THREADS) {   // 512 tasks
        int half = st & 1;
        int st2 = st >> 1;
        int b = st2 >> 4, l = st2 & 15;
        int batch = block0 + b;
        float in[11];
        const float* lf = led_features + (size_t)(batch * 16 + l) * 8;
        float4 f0 = *(const float4*)(lf);
        float4 f1 = *(const float4*)(lf + 4);
        in[0] = f0.x; in[1] = f0.y; in[2] = f0.z; in[3] = f0.w;
        in[4] = f1.x; in[5] = f1.y; in[6] = f1.z; in[7] = f1.w;
        const float* lp = led_positions + (size_t)(batch * 16 + l) * 3;
        in[8] = lp[0]; in[9] = lp[1]; in[10] = lp[2];
        if (half == 0) {
            const float* pp = prev_pos + (size_t)batch * 3;
            float dx = pp[0] - in[8], dy = pp[1] - in[9], dz = pp[2] - in[10];
            s_dist[b * 16 + l] = (dx * dx + dy * dy + dz * dz) * scale;
        }

        int c0 = half * 16;
        float* dst = s_rk + b * RKSTRIDE + l * 32 + c0;
        #pragma unroll
        for (int j4 = 0; j4 < 4; ++j4) {
            float4 a = *(const float4*)(s_kb1 + c0 + j4 * 4);
            #pragma unroll
            for (int d = 0; d < 11; ++d) {
                float4 w = *(const float4*)(s_kw1 + d * 32 + c0 + j4 * 4);
                a.x = fmaf(in[d], w.x, a.x);
                a.y = fmaf(in[d], w.y, a.y);
                a.z = fmaf(in[d], w.z, a.z);
                a.w = fmaf(in[d], w.w, a.w);
            }
            float4 r4;
            r4.x = fmaxf(a.x, 0.f); r4.y = fmaxf(a.y, 0.f);
            r4.z = fmaxf(a.z, 0.f); r4.w = fmaxf(a.w, 0.f);
            *(float4*)(dst + j4 * 4) = r4;
        }
    }

    // ---- Phase X: per (b,r) scalar work: gate MLP, x, bucket (192 tasks) ----
    if (tid < NB * 12) {
        int b = tid / 12, r = tid - b * 12;
        int batch = block0 + b;
        float rss = rss_t[batch * 12 + r];
        float gacc = s_gb2;
        #pragma unroll
        for (int k = 0; k < 16; ++k) {
            float h = fmaxf(fmaf(rss, s_gw1[k], s_gb1[k]), 0.f);
            gacc = fmaf(h, s_gw2[k], gacc);
        }
        float sig = __frcp_rn(1.f + __expf(-gacc));
        float iw = (rss > 0.5f) ? sig : 0.f;
        out_iw[batch * 12 + r] = iw;
        float x = rss * iw;
        int kb = 0;
        #pragma unroll
        for (int i4 = 0; i4 < 8; ++i4) {
            float4 tv = *(const float4*)(s_ts + i4 * 4);
            kb += (tv.x <= x) + (tv.y <= x) + (tv.z <= x) + (tv.w <= x);
        }
        s_xv[tid] = x;
        s_krow[tid] = kb * TSTRIDE;
    }
    __syncthreads();

    // ---- Phase G: thread-pair per (batch, r); each half owns 16 G columns,
    //      finalizes 8 leds; partner partials exchanged immediately ----
    {
        int half = tid & 1;
        int p = tid >> 1;                 // 0..191
        int b = p / 12, r = p - b * 12;
        int batch = block0 + b;
        int c0 = half * 16;
        int l0 = half * 8;                // own led base
        int lB = l0 ^ 8;                  // partner led base

        float x = s_xv[p];
        int krow = s_krow[p];

        // Ghat half = C_k + x * D_k  (16 cols)
        float G[16];
        const float* Crow = s_C + krow + c0;
        const float* Drow = s_D + krow + c0;
        #pragma unroll
        for (int k4 = 0; k4 < 4; ++k4) {
            float4 c4 = *(const float4*)(Crow + k4 * 4);
            float4 d4 = *(const float4*)(Drow + k4 * 4);
            G[k4 * 4 + 0] = fmaf(x, d4.x, c4.x);
            G[k4 * 4 + 1] = fmaf(x, d4.y, c4.y);
            G[k4 * 4 + 2] = fmaf(x, d4.z, c4.z);
            G[k4 * 4 + 3] = fmaf(x, d4.w, c4.w);
        }

        const float* rkb = s_rk + b * RKSTRIDE + c0;

        // fused: own-led partial + partner-led partial, exchange immediately
        float sA[8];
        #pragma unroll
        for (int i = 0; i < 8; ++i) {
            const float* rklA = rkb + (l0 + i) * 32;
            const float* rklB = rkb + (lB + i) * 32;
            float accA = -s_dist[b * 16 + l0 + i];
            float accB = 0.f;
            #pragma unroll
            for (int k4 = 0; k4 < 4; ++k4) {
                float4 vA = *(const float4*)(rklA + k4 * 4);
                float4 vB = *(const float4*)(rklB + k4 * 4);
                accA = fmaf(G[k4 * 4 + 0], vA.x, accA);
                accA = fmaf(G[k4 * 4 + 1], vA.y, accA);
                accA = fmaf(G[k4 * 4 + 2], vA.z, accA);
                accA = fmaf(G[k4 * 4 + 3], vA.w, accA);
                accB = fmaf(G[k4 * 4 + 0], vB.x, accB);
                accB = fmaf(G[k4 * 4 + 1], vB.y, accB);
                accB = fmaf(G[k4 * 4 + 2], vB.z, accB);
                accB = fmaf(G[k4 * 4 + 3], vB.w, accB);
            }
            sA[i] = accA + __shfl_xor_sync(0xffffffffu, accB, 1);
        }

        // distributed masked softmax over 16 leds; this thread owns 8
        unsigned m = s_mask[r];
        if (m == 0u) {
            #pragma unroll
            for (int i = 0; i < 8; ++i) sA[i] = 1.f / 16.f;
        } else {
            unsigned mo = (m >> l0) & 0xffu;
            float mx = -3.402823466e38f;
            #pragma unroll
            for (int i = 0; i < 8; ++i)
                if (mo & (1u << i)) mx = fmaxf(mx, sA[i]);
            mx = fmaxf(mx, __shfl_xor_sync(0xffffffffu, mx, 1));
            float part = 0.f;
            #pragma unroll
            for (int i = 0; i < 8; ++i) {
                float e = (mo & (1u << i)) ? __expf(sA[i] - mx) : 0.f;
                sA[i] = e;
                part += e;
            }
            float tot = part + __shfl_xor_sync(0xffffffffu, part, 1);
            float inv = __frcp_rn(tot);
            #pragma unroll
            for (int i = 0; i < 8; ++i) sA[i] *= inv;
        }

        float* dst = out_attn + (size_t)(batch * 12 + r) * 16 + l0;
        float4 o0, o1;
        o0.x = sA[0]; o0.y = sA[1]; o0.z = sA[2]; o0.w = sA[3];
        o1.x = sA[4]; o1.y = sA[5]; o1.z = sA[6]; o1.w = sA[7];
        *(float4*)(dst)     = o0;
        *(float4*)(dst + 4) = o1;
    }
}

extern "C" void kernel_launch(void* const* d_in, const int* in_sizes, int n_in,
                              void* d_out, int out_size) {
    const float* rss_t  = (const float*)d_in[0];
    const float* led_f  = (const float*)d_in[1];
    const float* led_p  = (const float*)d_in[2];
    const float* prevp  = (const float*)d_in[3];
    const int*   fmask  = (const int*)  d_in[4];
    const float* gw1    = (const float*)d_in[5];
    const float* gb1    = (const float*)d_in[6];
    const float* gw2    = (const float*)d_in[7];
    const float* gb2    = (const float*)d_in[8];
    const float* qw1    = (const float*)d_in[9];
    const float* qb1    = (const float*)d_in[10];
    const float* qw2    = (const float*)d_in[11];
    const float* qb2    = (const float*)d_in[12];
    const float* kw1    = (const float*)d_in[13];
    const float* kb1    = (const float*)d_in[14];
    const float* kw2    = (const float*)d_in[15];
    const float* kb2    = (const float*)d_in[16];
    const float* sigma  = (const float*)d_in[17];
    (void)kb2; (void)n_in; (void)out_size;

    int B = in_sizes[0] / 12;
    float* out = (float*)d_out;
    float* out_attn = out;                       // [B,12,16]
    float* out_iw   = out + (size_t)B * 192;     // [B,12]

    precompute_kernel<<<1, 256>>>(qw1, qb1, qw2, qb2, kw2);
    nearfield_kernel<<<B / NB, THREADS>>>(
        rss_t, led_f, led_p, prevp, fmask,
        gw1, gb1, gw2, gb2, kw1, kb1, sigma,
        out_attn, out_iw);
}

// round 15
// speedup vs baseline: 1.4292x; 1.4292x over previous
#include <cuda_runtime.h>

#define NB 16          // batches per block
#define THREADS 192    // = NB * 6 r-pairs * 2 threads
#define RKSTRIDE 516   // 16*32 + 4 pad floats
#define TSTRIDE 36     // bucket-table row stride (144B, 16B-aligned)

__device__ float g_C[33 * TSTRIDE];   // C_k[c]: constant part of Ghat per bucket
__device__ float g_D[33 * TSTRIDE];   // D_k[c]: slope part of Ghat per bucket
__device__ float g_ts[32];            // sorted thresholds

__device__ __forceinline__ unsigned long long fma2(unsigned long long a,
                                                   unsigned long long b,
                                                   unsigned long long c) {
    unsigned long long d;
    asm("fma.rn.f32x2 %0, %1, %2, %3;" : "=l"(d) : "l"(a), "l"(b), "l"(c));
    return d;
}
__device__ __forceinline__ unsigned long long pack2(float lo, float hi) {
    unsigned long long v;
    asm("mov.b64 %0, {%1, %2};" : "=l"(v) : "f"(lo), "f"(hi));
    return v;
}
__device__ __forceinline__ float sum2(unsigned long long v) {
    float lo, hi;
    asm("mov.b64 {%0, %1}, %2;" : "=f"(lo), "=f"(hi) : "l"(v));
    return lo + hi;
}

__global__ __launch_bounds__(256, 1) void precompute_kernel(
        const float* __restrict__ qw1,
        const float* __restrict__ qb1,
        const float* __restrict__ qw2,
        const float* __restrict__ qb2,
        const float* __restrict__ kw2) {
    __shared__ float sW[32 * 32];
    __shared__ float su[32];
    __shared__ float th_raw[32];
    __shared__ float s_sgn[32];
    __shared__ int   sidx[32];

    int t = threadIdx.x;              // 256 threads
    for (int e = t; e < 1024; e += 256) {
        int j = e >> 5, jp = e & 31;
        float s = 0.f;
        #pragma unroll
        for (int h = 0; h < 64; ++h)
            s = fmaf(qw2[j * 64 + h], kw2[jp * 64 + h], s);
        sW[e] = s;
    }
    if (t < 32) {
        int jp = t;
        float su_ = 0.f;
        #pragma unroll
        for (int h = 0; h < 64; ++h)
            su_ = fmaf(qb2[h], kw2[jp * 64 + h], su_);
        su[jp] = su_;
        float w = qw1[jp], b = qb1[jp];
        float th, sg;
        if (w > 0.f)      { th = -b / w; sg = 1.f; }
        else if (w < 0.f) { th = -b / w; sg = -1.f; }
        else              { th = (b > 0.f) ? -1e30f : 1e30f; sg = 1.f; }
        th_raw[jp] = th;
        s_sgn[jp] = sg;
    }
    __syncthreads();
    if (t < 32) {
        float mt = th_raw[t];
        int r = 0;
        #pragma unroll
        for (int i = 0; i < 32; ++i) {
            float o = th_raw[i];
            if (o < mt || (o == mt && i < t)) ++r;
        }
        sidx[r] = t;
        g_ts[r] = mt;
    }
    __syncthreads();
    for (int task = t; task < 33 * 32; task += 256) {
        int k = task >> 5, c = task & 31;
        float C = su[c], D = 0.f;
        for (int i = 0; i < 32; ++i) {
            int o = sidx[i];
            bool pos = (s_sgn[o] > 0.f);
            bool active = pos ? (i < k) : (i >= k);
            if (active) {
                float wv = sW[o * 32 + c];
                C = fmaf(qb1[o], wv, C);
                D = fmaf(qw1[o], wv, D);
            }
        }
        g_C[k * TSTRIDE + c] = C;
        g_D[k * TSTRIDE + c] = D;
    }
}

__global__ __launch_bounds__(THREADS, 4) void nearfield_kernel(
    const float* __restrict__ rss_t,          // [B,12]
    const float* __restrict__ led_features,   // [B,16,8]
    const float* __restrict__ led_positions,  // [B,16,3]
    const float* __restrict__ prev_pos,       // [B,3]
    const int*   __restrict__ freq_mask,      // [12,16]
    const float* __restrict__ gw1, const float* __restrict__ gb1,
    const float* __restrict__ gw2, const float* __restrict__ gb2,
    const float* __restrict__ kw1, const float* __restrict__ kb1,
    const float* __restrict__ sigma,
    float* __restrict__ out_attn,             // [B,12,16]
    float* __restrict__ out_iw)               // [B,12]
{
    __shared__ __align__(16) float s_kw1[11 * 32];
    __shared__ __align__(16) float s_kb1[32];
    __shared__ __align__(16) float s_C[33 * TSTRIDE];
    __shared__ __align__(16) float s_D[33 * TSTRIDE];
    __shared__ __align__(16) float s_ts[32];
    __shared__ float s_gw1[16], s_gb1[16], s_gw2[16];
    __shared__ float s_gb2, s_scale;
    __shared__ unsigned s_mask[12];
    __shared__ __align__(16) float s_rk[NB * RKSTRIDE];
    __shared__ float s_dist[NB * 16];
    __shared__ float s_xv[NB * 12];           // x per (b,r)
    __shared__ int   s_krow[NB * 12];         // bucket row offset per (b,r)

    const int tid = threadIdx.x;

    // ---- cooperative staging ----
    for (int i = tid; i < 352; i += THREADS) s_kw1[i] = kw1[i];
    for (int i = tid; i < 33 * TSTRIDE; i += THREADS) {
        s_C[i] = g_C[i];
        s_D[i] = g_D[i];
    }
    if (tid < 32) {
        s_kb1[tid] = kb1[tid];
        s_ts[tid]  = g_ts[tid];
    }
    if (tid < 16) {
        s_gw1[tid] = gw1[tid];
        s_gb1[tid] = gb1[tid];
        s_gw2[tid] = gw2[tid];
    }
    if (tid == 0) {
        float sg = sigma[0];
        s_gb2 = gb2[0];
        s_scale = 0.5f / (sg * sg);
    }
    if (tid < 12) {
        unsigned m = 0;
        #pragma unroll
        for (int l = 0; l < 16; ++l)
            if (freq_mask[tid * 16 + l] != 0) m |= (1u << l);
        s_mask[tid] = m;
    }
    __syncthreads();

    const int block0 = blockIdx.x * NB;
    const float scale = s_scale;

    // ---- Phase K: subtask (b, l, half): 16 cols of rk = relu(led_in@kw1+kb1) ----
    for (int st = tid; st < NB * 16 * 2; st += THREADS) {   // 512 tasks
        int half = st & 1;
        int st2 = st >> 1;
        int b = st2 >> 4, l = st2 & 15;
        int batch = block0 + b;
        float in[11];
        const float* lf = led_features + (size_t)(batch * 16 + l) * 8;
        float4 f0 = *(const float4*)(lf);
        float4 f1 = *(const float4*)(lf + 4);
        in[0] = f0.x; in[1] = f0.y; in[2] = f0.z; in[3] = f0.w;
        in[4] = f1.x; in[5] = f1.y; in[6] = f1.z; in[7] = f1.w;
        const float* lp = led_positions + (size_t)(batch * 16 + l) * 3;
        in[8] = lp[0]; in[9] = lp[1]; in[10] = lp[2];
        if (half == 0) {
            const float* pp = prev_pos + (size_t)batch * 3;
            float dx = pp[0] - in[8], dy = pp[1] - in[9], dz = pp[2] - in[10];
            s_dist[b * 16 + l] = (dx * dx + dy * dy + dz * dz) * scale;
        }

        int c0 = half * 16;
        float* dst = s_rk + b * RKSTRIDE + l * 32 + c0;
        #pragma unroll
        for (int j4 = 0; j4 < 4; ++j4) {
            float4 a = *(const float4*)(s_kb1 + c0 + j4 * 4);
            #pragma unroll
            for (int d = 0; d < 11; ++d) {
                float4 w = *(const float4*)(s_kw1 + d * 32 + c0 + j4 * 4);
                a.x = fmaf(in[d], w.x, a.x);
                a.y = fmaf(in[d], w.y, a.y);
                a.z = fmaf(in[d], w.z, a.z);
                a.w = fmaf(in[d], w.w, a.w);
            }
            float4 r4;
            r4.x = fmaxf(a.x, 0.f); r4.y = fmaxf(a.y, 0.f);
            r4.z = fmaxf(a.z, 0.f); r4.w = fmaxf(a.w, 0.f);
            *(float4*)(dst + j4 * 4) = r4;
        }
    }

    // ---- Phase X: per (b,r) scalar work: gate MLP, x, bucket (192 tasks) ----
    {
        int b = tid / 12, r = tid - b * 12;
        int batch = block0 + b;
        float rss = rss_t[batch * 12 + r];
        float gacc = s_gb2;
        #pragma unroll
        for (int k = 0; k < 16; ++k) {
            float h = fmaxf(fmaf(rss, s_gw1[k], s_gb1[k]), 0.f);
            gacc = fmaf(h, s_gw2[k], gacc);
        }
        float sig = __frcp_rn(1.f + __expf(-gacc));
        float iw = (rss > 0.5f) ? sig : 0.f;
        out_iw[batch * 12 + r] = iw;
        float x = rss * iw;
        int kb = 0;
        #pragma unroll
        for (int i4 = 0; i4 < 8; ++i4) {
            float4 tv = *(const float4*)(s_ts + i4 * 4);
            kb += (tv.x <= x) + (tv.y <= x) + (tv.z <= x) + (tv.w <= x);
        }
        s_xv[tid] = x;
        s_krow[tid] = kb * TSTRIDE;
    }
    __syncthreads();

    // ---- Phase G: thread-pair per (batch, r-pair); each half owns 16 cols,
    //      finalizes 8 leds for BOTH r values (rk LDS amortized over 2 r) ----
    {
        int half = tid & 1;
        int p = tid >> 1;                 // 0..95
        int b = p / 6, r2 = p - b * 6;
        int r0 = r2 * 2, r1 = r0 + 1;
        int batch = block0 + b;
        int c0 = half * 16;
        int l0 = half * 8;                // own led base
        int lB0 = l0 ^ 8;                 // partner led base

        float x0 = s_xv[b * 12 + r0];
        float x1 = s_xv[b * 12 + r1];
        int krow0 = s_krow[b * 12 + r0];
        int krow1 = s_krow[b * 12 + r1];

        unsigned long long X0 = pack2(x0, x0);
        unsigned long long X1 = pack2(x1, x1);

        // packed Ghat halves: G[c],G[c+1] pairs for both r
        unsigned long long G0[8], G1[8];
        {
            const ulonglong2* C2 = (const ulonglong2*)(s_C + krow0 + c0);
            const ulonglong2* D2 = (const ulonglong2*)(s_D + krow0 + c0);
            #pragma unroll
            for (int k = 0; k < 4; ++k) {
                ulonglong2 c2 = C2[k], d2 = D2[k];
                G0[2 * k]     = fma2(X0, d2.x, c2.x);
                G0[2 * k + 1] = fma2(X0, d2.y, c2.y);
            }
            const ulonglong2* C2b = (const ulonglong2*)(s_C + krow1 + c0);
            const ulonglong2* D2b = (const ulonglong2*)(s_D + krow1 + c0);
            #pragma unroll
            for (int k = 0; k < 4; ++k) {
                ulonglong2 c2 = C2b[k], d2 = D2b[k];
                G1[2 * k]     = fma2(X1, d2.x, c2.x);
                G1[2 * k + 1] = fma2(X1, d2.y, c2.y);
            }
        }

        const float* rkb = s_rk + b * RKSTRIDE + c0;
        float s0[8], s1[8];
        #pragma unroll
        for (int i = 0; i < 8; ++i) {
            float dist = s_dist[b * 16 + l0 + i];
            const ulonglong2* vA = (const ulonglong2*)(rkb + (l0 + i) * 32);
            const ulonglong2* vB = (const ulonglong2*)(rkb + (lB0 + i) * 32);
            unsigned long long a0 = pack2(-dist, 0.f);
            unsigned long long a1 = a0;
            unsigned long long b0 = 0ull, b1 = 0ull;
            #pragma unroll
            for (int k = 0; k < 4; ++k) {
                ulonglong2 v = vA[k];
                a0 = fma2(G0[2 * k], v.x, a0);
                a0 = fma2(G0[2 * k + 1], v.y, a0);
                a1 = fma2(G1[2 * k], v.x, a1);
                a1 = fma2(G1[2 * k + 1], v.y, a1);
            }
            #pragma unroll
            for (int k = 0; k < 4; ++k) {
                ulonglong2 v = vB[k];
                b0 = fma2(G0[2 * k], v.x, b0);
                b0 = fma2(G0[2 * k + 1], v.y, b0);
                b1 = fma2(G1[2 * k], v.x, b1);
                b1 = fma2(G1[2 * k + 1], v.y, b1);
            }
            float pb0 = sum2(b0), pb1 = sum2(b1);
            s0[i] = sum2(a0) + __shfl_xor_sync(0xffffffffu, pb0, 1);
            s1[i] = sum2(a1) + __shfl_xor_sync(0xffffffffu, pb1, 1);
        }

        // distributed masked softmax (convergent shuffles; m==0 via final select)
        unsigned m0 = s_mask[r0];
        unsigned m1 = s_mask[r1];
        unsigned mo0 = (m0 >> l0) & 0xffu;
        unsigned mo1 = (m1 >> l0) & 0xffu;

        float mx0 = -3.402823466e38f, mx1 = -3.402823466e38f;
        #pragma unroll
        for (int i = 0; i < 8; ++i) {
            if (mo0 & (1u << i)) mx0 = fmaxf(mx0, s0[i]);
            if (mo1 & (1u << i)) mx1 = fmaxf(mx1, s1[i]);
        }
        mx0 = fmaxf(mx0, __shfl_xor_sync(0xffffffffu, mx0, 1));
        mx1 = fmaxf(mx1, __shfl_xor_sync(0xffffffffu, mx1, 1));

        float part0 = 0.f, part1 = 0.f;
        #pragma unroll
        for (int i = 0; i < 8; ++i) {
            float e0 = (mo0 & (1u << i)) ? __expf(s0[i] - mx0) : 0.f;
            float e1 = (mo1 & (1u << i)) ? __expf(s1[i] - mx1) : 0.f;
            s0[i] = e0; part0 += e0;
            s1[i] = e1; part1 += e1;
        }
        float tot0 = part0 + __shfl_xor_sync(0xffffffffu, part0, 1);
        float tot1 = part1 + __shfl_xor_sync(0xffffffffu, part1, 1);
        float inv0 = __frcp_rn(tot0);
        float inv1 = __frcp_rn(tot1);
        #pragma unroll
        for (int i = 0; i < 8; ++i) {
            s0[i] = (m0 == 0u) ? (1.f / 16.f) : s0[i] * inv0;
            s1[i] = (m1 == 0u) ? (1.f / 16.f) : s1[i] * inv1;
        }

        float* dst0 = out_attn + (size_t)(batch * 12 + r0) * 16 + l0;
        float* dst1 = out_attn + (size_t)(batch * 12 + r1) * 16 + l0;
        float4 o;
        o.x = s0[0]; o.y = s0[1]; o.z = s0[2]; o.w = s0[3];
        *(float4*)(dst0) = o;
        o.x = s0[4]; o.y = s0[5]; o.z = s0[6]; o.w = s0[7];
        *(float4*)(dst0 + 4) = o;
        o.x = s1[0]; o.y = s1[1]; o.z = s1[2]; o.w = s1[3];
        *(float4*)(dst1) = o;
        o.x = s1[4]; o.y = s1[5]; o.z = s1[6]; o.w = s1[7];
        *(float4*)(dst1 + 4) = o;
    }
}

extern "C" void kernel_launch(void* const* d_in, const int* in_sizes, int n_in,
                              void* d_out, int out_size) {
    const float* rss_t  = (const float*)d_in[0];
    const float* led_f  = (const float*)d_in[1];
    const float* led_p  = (const float*)d_in[2];
    const float* prevp  = (const float*)d_in[3];
    const int*   fmask  = (const int*)  d_in[4];
    const float* gw1    = (const float*)d_in[5];
    const float* gb1    = (const float*)d_in[6];
    const float* gw2    = (const float*)d_in[7];
    const float* gb2    = (const float*)d_in[8];
    const float* qw1    = (const float*)d_in[9];
    const float* qb1    = (const float*)d_in[10];
    const float* qw2    = (const float*)d_in[11];
    const float* qb2    = (const float*)d_in[12];
    const float* kw1    = (const float*)d_in[13];
    const float* kb1    = (const float*)d_in[14];
    const float* kw2    = (const float*)d_in[15];
    const float* kb2    = (const float*)d_in[16];
    const float* sigma  = (const float*)d_in[17];
    (void)kb2; (void)n_in; (void)out_size;

    int B = in_sizes[0] / 12;
    float* out = (float*)d_out;
    float* out_attn = out;                       // [B,12,16]
    float* out_iw   = out + (size_t)B * 192;     // [B,12]

    precompute_kernel<<<1, 256>>>(qw1, qb1, qw2, qb2, kw2);
    nearfield_kernel<<<B / NB, THREADS>>>(
        rss_t, led_f, led_p, prevp, fmask,
        gw1, gb1, gw2, gb2, kw1, kb1, sigma,
        out_attn, out_iw);
}